// round 1
// baseline (speedup 1.0000x reference)
#include <cuda_runtime.h>
#include <cstdint>

// Differentiable A* forward (training mode), N=4096, Tmax=N/4.
// Single persistent block: all state in SMEM/registers; one weighted_adj row
// (16KB) fetched from GMEM per expansion step.

#define NMAX 4096
#define TPB  1024
#define VPT  4          // nodes per thread (NMAX / TPB)

__global__ __launch_bounds__(TPB, 1)
void astar_persistent_kernel(const int* __restrict__ start_p,
                             const int* __restrict__ goal_p,
                             const float* __restrict__ h_in,
                             const float* __restrict__ wadj,
                             float* __restrict__ out,
                             int N)
{
    __shared__ float sm_g[NMAX];
    __shared__ int   sm_parents[NMAX];
    __shared__ unsigned long long sm_warp[TPB / 32];
    __shared__ unsigned long long sm_key;

    const int tid  = threadIdx.x;
    const int lane = tid & 31;
    const int wid  = tid >> 5;
    const int start = start_p[0];
    const int goal  = goal_p[0];
    const float inv_sqrt_n = 1.0f / sqrtf((float)N);   // N=4096 -> exactly 1/64
    const int Tmax = N / 4;                            // TMAX_RATIO = 0.25
    const int j0 = tid * VPT;

    // -------- init state --------
    float hreg[VPT], greg[VPT];
    bool  open_[VPT], hist_[VPT];
    {
        const float* row0 = wadj + (size_t)start * N;
        #pragma unroll
        for (int k = 0; k < VPT; k++) {
            int j = j0 + k;
            hreg[k] = h_in[j];
            // reference zeroes the diagonal of weighted_adj before g0 = wadj[start]
            float g = (j == start) ? 0.0f : row0[j];
            greg[k] = g;
            sm_g[j] = g;
            sm_parents[j] = goal;        // parents0 = goal_index
            open_[k] = (j == start);
            hist_[k] = false;
        }
    }
    __syncthreads();

    bool done = false;
    int  t_final = 0;

    for (int t = 0; t < Tmax; t++) {
        // ---- build selection key: argmax of expf(-f/64)*open, tie -> lowest idx ----
        unsigned long long key = 0ULL;
        #pragma unroll
        for (int k = 0; k < VPT; k++) {
            if (open_[k]) {
                float f   = 0.5f * greg[k] + 0.5f * hreg[k];
                float val = expf(-f * inv_sqrt_n);          // val > 0 always
                unsigned long long kk =
                    ((unsigned long long)__float_as_uint(val) << 32)
                    | (unsigned int)(NMAX - 1 - (j0 + k));  // larger = lower index
                if (kk > key) key = kk;
            }
        }
        // warp-level u64 max
        #pragma unroll
        for (int off = 16; off > 0; off >>= 1) {
            unsigned long long o = __shfl_down_sync(0xFFFFFFFFu, key, off);
            if (o > key) key = o;
        }
        if (lane == 0) sm_warp[wid] = key;
        __syncthreads();
        if (wid == 0) {
            unsigned long long k2 = sm_warp[lane];
            #pragma unroll
            for (int off = 16; off > 0; off >>= 1) {
                unsigned long long o = __shfl_down_sync(0xFFFFFFFFu, k2, off);
                if (o > k2) k2 = o;
            }
            if (lane == 0) sm_key = k2;
        }
        __syncthreads();
        key = sm_key;
        // empty-open fallback: reference argmax of all-zero y returns index 0
        const int ind = (key == 0ULL) ? 0 : (NMAX - 1 - (int)(key & 0xFFFu));

        // ---- fetch the selected row (only varying GMEM traffic in the loop) ----
        const float  g_ind = sm_g[ind];   // never written this iteration (idx[ind]=0)
        const float4 wv = reinterpret_cast<const float4*>(wadj + (size_t)ind * N)[tid];
        float w[VPT] = {wv.x, wv.y, wv.z, wv.w};

        // ---- state update: open2/hist2 + neighbor relax (idx == neighbor) ----
        #pragma unroll
        for (int k = 0; k < VPT; k++) {
            int j = j0 + k;
            if (j == ind) {
                open_[k] = false;         // open2 = clip(open - snm)
                hist_[k] = true;          // hist2 = clip(hist + snm)
            } else if (w[k] != 0.0f && !open_[k] && !hist_[k]) {
                float gn = g_ind + w[k];  // g2 = g[ind] + wadj[ind, j]
                greg[k] = gn;
                sm_g[j] = gn;
                sm_parents[j] = ind;
                open_[k] = true;          // open3 = open2 | idx
            }
        }

        t_final = t;                       // updated every non-frozen step
        if (ind == goal) done = true;      // solved -> state freezes afterward
        __syncthreads();
        if (done) break;
    }

    // -------- outputs: [0,N) hist (f32), [N,2N) path_maps (as f32) --------
    #pragma unroll
    for (int k = 0; k < VPT; k++) {
        int j = j0 + k;
        out[j]     = hist_[k] ? 1.0f : 0.0f;
        out[N + j] = 0.0f;
    }
    __syncthreads();

    // -------- backtrack (serial, thread 0): t_final hops from parents[goal] ----
    if (tid == 0) {
        out[N + goal] = 1.0f;              // path0 = goal one-hot
        int loc = sm_parents[goal];
        for (int i = 0; i < t_final; i++) {
            out[N + loc] = 1.0f;
            loc = sm_parents[loc];
        }
    }
}

extern "C" void kernel_launch(void* const* d_in, const int* in_sizes, int n_in,
                              void* d_out, int out_size)
{
    const int*   start = (const int*)  d_in[0];
    const int*   goal  = (const int*)  d_in[1];
    const float* h     = (const float*)d_in[2];
    // d_in[3] = nodes (unused), d_in[4] = adj (redundant: wadj != 0 <=> adj == 1)
    const float* wadj  = (const float*)d_in[5];
    float* out = (float*)d_out;
    int N = in_sizes[2];                   // 4096

    astar_persistent_kernel<<<1, TPB>>>(start, goal, h, wadj, out, N);
}